// round 1
// baseline (speedup 1.0000x reference)
#include <cuda_runtime.h>
#include <math.h>
#include <cstddef>

// ---------------- constants ----------------
#define BN_SC 0.9999950000374997f   // 1/sqrt(1+1e-5) as float
#define NB 8
#define NC 64
#define NH_ 8
#define HD_ 8
#define HW128 128
#define NS 126                       // gabor conv valid size
#define NIMG (NB*NC)                 // 512
#define ATTN_SCALE 0.35355339059327373f

// ---------------- scratch (static __device__, no allocs) ----------------
__device__ float g_local[NB*NC*HW128*HW128];
__device__ float g_qkv [NB*3*NC*HW128*HW128];
__device__ float g_o   [NB*NC*HW128*HW128];
__device__ float g_sum [NB*NC*HW128*HW128];
__device__ float g_dw  [NB*NC*HW128*HW128];
__device__ float g_xc  [NIMG*NS*NS];
__device__ float g_fft [NIMG*NS*NS];
__device__ float g_xc2 [NIMG*NS*NS];
__device__ float g_cr1 [NIMG*NS*NS];
__device__ float g_ci1 [NIMG*NS*NS];
__device__ float g_cr2 [NIMG*NS*NS];
__device__ float g_ci2 [NIMG*NS*NS];
__device__ float g_p   [NIMG*NS*NS];
__device__ float g_q   [NIMG*125*125];
__device__ float g_r   [NIMG*62*62];
__device__ float g_s   [NIMG*31*31];
__device__ float g_t   [NB*NC*HW128*HW128];
__device__ float g_u   [NB*NC*HW128*HW128];
__device__ float g_v   [NB*NC*HW128*HW128];
__device__ float g_Cm  [NS*NS];
__device__ float g_Sm  [NS*NS];

// ---------------- generic direct conv (K in {1,3}) ----------------
// block 256 threads = 16x16 output tile; 8 output channels per block (reg blocked)
__global__ void conv_k(const float* __restrict__ in, const float* __restrict__ w,
                       const float* __restrict__ bias, const float* __restrict__ bng,
                       const float* __restrict__ bnb, float* __restrict__ out,
                       int Cin, int Hin, int Win, int Cout, int CoutTotal, int coOff,
                       int K, int stride, int pad, int Hout, int Wout,
                       int act, int accum)
{
    __shared__ float sIn[33*33];
    __shared__ float sW[8*64*9];
    int tileW = (Wout + 15) >> 4;
    int tX = blockIdx.x % tileW, tY = blockIdx.x / tileW;
    int ow0 = tX << 4, oh0 = tY << 4;
    int co0 = blockIdx.y << 3;
    int b   = blockIdx.z;
    int tid = threadIdx.x;
    int KK = K * K;
    int cikk = Cin * KK;
    int nW = 8 * cikk;
    for (int t = tid; t < nW; t += 256) {
        int co = t / cikk;
        sW[t] = (co0 + co < Cout) ? w[(size_t)(co0 + co) * cikk + (t - co * cikk)] : 0.f;
    }
    int span = 15 * stride + K;
    int ih0 = oh0 * stride - pad, iw0 = ow0 * stride - pad;
    float acc[8];
#pragma unroll
    for (int i = 0; i < 8; i++) acc[i] = 0.f;
    const float* inb = in + (size_t)b * Cin * Hin * Win;
    int ty = tid >> 4, tx = tid & 15;
    for (int ci = 0; ci < Cin; ci++) {
        __syncthreads();
        const float* ip = inb + (size_t)ci * Hin * Win;
        int ss = span * span;
        for (int t = tid; t < ss; t += 256) {
            int iy = t / span, ix = t - iy * span;
            int gy = ih0 + iy, gx = iw0 + ix;
            sIn[t] = (gy >= 0 && gy < Hin && gx >= 0 && gx < Win) ? ip[(size_t)gy * Win + gx] : 0.f;
        }
        __syncthreads();
        int base = (ty * stride) * span + tx * stride;
        if (K == 3) {
            float r0 = sIn[base],            r1 = sIn[base+1],            r2 = sIn[base+2];
            float r3 = sIn[base+span],       r4 = sIn[base+span+1],       r5 = sIn[base+span+2];
            float r6 = sIn[base+2*span],     r7 = sIn[base+2*span+1],     r8 = sIn[base+2*span+2];
#pragma unroll
            for (int co = 0; co < 8; co++) {
                const float* wp = &sW[(co * Cin + ci) * 9];
                acc[co] += r0*wp[0] + r1*wp[1] + r2*wp[2]
                         + r3*wp[3] + r4*wp[4] + r5*wp[5]
                         + r6*wp[6] + r7*wp[7] + r8*wp[8];
            }
        } else {
            float r = sIn[base];
#pragma unroll
            for (int co = 0; co < 8; co++) acc[co] += r * sW[co * Cin + ci];
        }
    }
    int oh = oh0 + ty, ow = ow0 + tx;
    if (oh < Hout && ow < Wout) {
        for (int co = 0; co < 8; co++) {
            int gco = co0 + co;
            if (gco >= Cout) break;
            float v = acc[co];
            if (bias) v += bias[gco];
            if (bng)  v = v * (bng[gco] * BN_SC) + bnb[gco];
            if (act == 1) v = fmaxf(v, 0.f);
            else if (act == 2) v = fminf(fmaxf(v, 0.f), 6.f);
            size_t oidx = (((size_t)b * CoutTotal + coOff + gco) * Hout + oh) * Wout + ow;
            if (accum) out[oidx] += v; else out[oidx] = v;
        }
    }
}

// ---------------- DFT matrices ----------------
__global__ void initdft_k()
{
    int idx = blockIdx.x * blockDim.x + threadIdx.x;
    if (idx >= NS * NS) return;
    int u = idx / NS, h = idx % NS;
    int m = (u * h) % NS;
    float xx = (2.0f * (float)m) / (float)NS;
    g_Cm[idx] = cospif(xx);
    g_Sm[idx] = sinpif(xx);
}

// ---------------- batched complex GEMM (126x126, shared DFT factor) ----------------
// leftF=1: C = F @ X ; leftF=0: C = X @ F.  F = (Fr, fiSign*Fi). X complex (Xi may be null).
__global__ void cgemm_k(const float* __restrict__ Fr, const float* __restrict__ Fi, float fiSign,
                        const float* __restrict__ Xr, const float* __restrict__ Xi,
                        float* __restrict__ Cr, float* __restrict__ Ci,
                        int leftF, int doMag, float magScale, float* __restrict__ Mag)
{
    __shared__ __align__(16) float sAr[8][64], sAi[8][64], sBr[8][64], sBi[8][64];
    size_t off = (size_t)blockIdx.z * (NS * NS);
    int row0 = blockIdx.y * 64, col0 = blockIdx.x * 64;
    int tx = threadIdx.x, ty = threadIdx.y;
    int tid = ty * 16 + tx;
    float aR[4][4], aI[4][4];
#pragma unroll
    for (int r = 0; r < 4; r++)
#pragma unroll
        for (int c = 0; c < 4; c++) { aR[r][c] = 0.f; aI[r][c] = 0.f; }

    for (int k0 = 0; k0 < NS; k0 += 8) {
        for (int t = tid; t < 512; t += 256) {
            int kk = t >> 6, r = t & 63;
            int gk = k0 + kk;
            int gi = row0 + r;
            float ar = 0.f, ai = 0.f;
            if (gi < NS && gk < NS) {
                if (leftF) { ar = Fr[gi * NS + gk]; ai = fiSign * Fi[gi * NS + gk]; }
                else { size_t o = off + (size_t)gi * NS + gk; ar = Xr[o]; ai = Xi ? Xi[o] : 0.f; }
            }
            sAr[kk][r] = ar; sAi[kk][r] = ai;
            int gj = col0 + r;
            float br = 0.f, bi = 0.f;
            if (gj < NS && gk < NS) {
                if (leftF) { size_t o = off + (size_t)gk * NS + gj; br = Xr[o]; bi = Xi ? Xi[o] : 0.f; }
                else { br = Fr[gk * NS + gj]; bi = fiSign * Fi[gk * NS + gj]; }
            }
            sBr[kk][r] = br; sBi[kk][r] = bi;
        }
        __syncthreads();
#pragma unroll
        for (int kk = 0; kk < 8; kk++) {
            float4 a4r = *(const float4*)&sAr[kk][ty * 4];
            float4 a4i = *(const float4*)&sAi[kk][ty * 4];
            float4 b4r = *(const float4*)&sBr[kk][tx * 4];
            float4 b4i = *(const float4*)&sBi[kk][tx * 4];
            float ar[4] = {a4r.x, a4r.y, a4r.z, a4r.w};
            float ai[4] = {a4i.x, a4i.y, a4i.z, a4i.w};
            float br[4] = {b4r.x, b4r.y, b4r.z, b4r.w};
            float bi[4] = {b4i.x, b4i.y, b4i.z, b4i.w};
#pragma unroll
            for (int r = 0; r < 4; r++)
#pragma unroll
                for (int c = 0; c < 4; c++) {
                    aR[r][c] += ar[r] * br[c] - ai[r] * bi[c];
                    aI[r][c] += ar[r] * bi[c] + ai[r] * br[c];
                }
        }
        __syncthreads();
    }
#pragma unroll
    for (int r = 0; r < 4; r++)
#pragma unroll
        for (int c = 0; c < 4; c++) {
            int gi = row0 + ty * 4 + r, gj = col0 + tx * 4 + c;
            if (gi < NS && gj < NS) {
                size_t o = off + (size_t)gi * NS + gj;
                if (doMag) Mag[o] = sqrtf(aR[r][c] * aR[r][c] + aI[r][c] * aI[r][c]) * magScale;
                else { Cr[o] = aR[r][c]; Ci[o] = aI[r][c]; }
            }
        }
}

// ---------------- pointwise: high-pass mask in freq domain ----------------
__global__ void mask_k(float* __restrict__ zr, float* __restrict__ zi, int n)
{
    int idx = blockIdx.x * blockDim.x + threadIdx.x;
    if (idx >= n) return;
    int within = idx % (NS * NS);
    int u = within / NS, v = within % NS;
    int su = (u < 63) ? u : u - NS;
    int sv = (v < 63) ? v : v - NS;
    float r = zr[idx], i = zi[idx];
    float s = (su * su + sv * sv > 1600) ? sqrtf(r * r + i * i) : 0.f;
    zr[idx] = r * s;
    zi[idx] = i * s;
}

// ---------------- combine fft branch with passthrough ----------------
__global__ void combine_k(const float* __restrict__ fft, const float* __restrict__ xc,
                          const float* __restrict__ gbw, float* __restrict__ out, int n)
{
    int idx = blockIdx.x * blockDim.x + threadIdx.x;
    if (idx >= n) return;
    float w0 = fmaxf(gbw[0], 0.f), w1 = fmaxf(gbw[1], 0.f);
    float d = w0 + w1 + 1e-8f;
    out[idx] = (w0 / d) * fft[idx] + (w1 / d) * xc[idx];
}

// ---------------- maxpools ----------------
__global__ void mp21_k(const float* __restrict__ in, float* __restrict__ out)
{
    int idx = blockIdx.x * blockDim.x + threadIdx.x;
    int n = NIMG * 125 * 125;
    if (idx >= n) return;
    int w = idx % 125, h = (idx / 125) % 125, ch = idx / (125 * 125);
    const float* p = in + (size_t)ch * NS * NS + (size_t)h * NS + w;
    out[idx] = fmaxf(fmaxf(p[0], p[1]), fmaxf(p[NS], p[NS + 1]));
}
__global__ void mp22_k(const float* __restrict__ in, float* __restrict__ out)
{
    int idx = blockIdx.x * blockDim.x + threadIdx.x;
    int n = NIMG * 31 * 31;
    if (idx >= n) return;
    int w = idx % 31, h = (idx / 31) % 31, ch = idx / (31 * 31);
    const float* p = in + (size_t)ch * 62 * 62 + (size_t)(2 * h) * 62 + 2 * w;
    out[idx] = fmaxf(fmaxf(p[0], p[1]), fmaxf(p[62], p[63]));
}

// ---------------- bilinear resize 31 -> 128 (jax half-pixel, clamp) ----------------
__global__ void resize_k(const float* __restrict__ in, float* __restrict__ out)
{
    int idx = blockIdx.x * blockDim.x + threadIdx.x;
    int n = NIMG * HW128 * HW128;
    if (idx >= n) return;
    int x = idx & 127, y = (idx >> 7) & 127, ch = idx >> 14;
    const float sc = 31.f / 128.f;
    float sy = fminf(fmaxf((y + 0.5f) * sc - 0.5f, 0.f), 30.f);
    float sx = fminf(fmaxf((x + 0.5f) * sc - 0.5f, 0.f), 30.f);
    int y0 = (int)floorf(sy); float fy = sy - y0; int y1 = min(y0 + 1, 30);
    int x0 = (int)floorf(sx); float fx = sx - x0; int x1 = min(x0 + 1, 30);
    const float* p = in + (size_t)ch * 961;
    float v = (1.f - fy) * ((1.f - fx) * p[y0 * 31 + x0] + fx * p[y0 * 31 + x1])
            + fy         * ((1.f - fx) * p[y1 * 31 + x0] + fx * p[y1 * 31 + x1]);
    out[idx] = v;
}

// ---------------- log_softmax over channels ----------------
__global__ void lsm_k(const float* __restrict__ in, float* __restrict__ out)
{
    int gid = blockIdx.x * blockDim.x + threadIdx.x;
    if (gid >= NB * HW128 * HW128) return;
    int b = gid >> 14, p = gid & 16383;
    size_t base = (size_t)b * NC * 16384 + p;
    float mx = -1e30f;
    for (int c = 0; c < NC; c++) mx = fmaxf(mx, in[base + (size_t)c * 16384]);
    float s = 0.f;
    for (int c = 0; c < NC; c++) s += expf(in[base + (size_t)c * 16384] - mx);
    float l = logf(s);
    for (int c = 0; c < NC; c++) {
        size_t o = base + (size_t)c * 16384;
        out[o] = in[o] - mx - l;
    }
}

// ---------------- windowed attention ----------------
__global__ void attn_k(const float* __restrict__ qkv, const float* __restrict__ rpb,
                       const int* __restrict__ relidx, float* __restrict__ o)
{
    __shared__ float sk[64][8];
    __shared__ float sv[64][8];
    int win = blockIdx.x;            // 0..255
    int gh = win >> 4, gw = win & 15;
    int n = blockIdx.y, b = blockIdx.z;
    int i = threadIdx.x;             // token 0..63
    int hi = gh * 8 + (i >> 3), wi = gw * 8 + (i & 7);
    float q[8];
#pragma unroll
    for (int d = 0; d < 8; d++) {
        int cq = n * 8 + d;
        size_t sp = (size_t)hi * 128 + wi;
        q[d]      = qkv[(((size_t)b * 192 + cq)       * 16384) + sp];
        sk[i][d]  = qkv[(((size_t)b * 192 + 64 + cq)  * 16384) + sp];
        sv[i][d]  = qkv[(((size_t)b * 192 + 128 + cq) * 16384) + sp];
    }
    __syncthreads();
    float logits[64];
    float mx = -1e30f;
#pragma unroll
    for (int j = 0; j < 64; j++) {
        float dot = 0.f;
#pragma unroll
        for (int d = 0; d < 8; d++) dot += q[d] * sk[j][d];
        float l = dot * ATTN_SCALE + rpb[relidx[i * 64 + j] * 8 + n];
        logits[j] = l;
        mx = fmaxf(mx, l);
    }
    float se = 0.f;
#pragma unroll
    for (int j = 0; j < 64; j++) { float e = expf(logits[j] - mx); logits[j] = e; se += e; }
    float inv = 1.f / se;
    float od[8];
#pragma unroll
    for (int d = 0; d < 8; d++) od[d] = 0.f;
#pragma unroll
    for (int j = 0; j < 64; j++) {
#pragma unroll
        for (int d = 0; d < 8; d++) od[d] += logits[j] * sv[j][d];
    }
#pragma unroll
    for (int d = 0; d < 8; d++)
        o[(((size_t)b * 64 + n * 8 + d) * 128 + hi) * 128 + wi] = od[d] * inv;
}

// ---------------- directional pools + add local ----------------
__global__ void poolsum_k(const float* __restrict__ o, const float* __restrict__ loc,
                          float* __restrict__ out)
{
    int idx = blockIdx.x * blockDim.x + threadIdx.x;
    int n = NB * NC * HW128 * HW128;
    if (idx >= n) return;
    int w = idx & 127, h = (idx >> 7) & 127;
    size_t chbase = (size_t)(idx >> 14) * 16384;
    float sx = 0.f;
#pragma unroll
    for (int t = -3; t <= 4; t++) {
        int r = h + t;
        if (r >= 0 && r <= 128) { if (r == 128) r = 126; sx += o[chbase + (size_t)r * 128 + w]; }
    }
    float sy = 0.f;
#pragma unroll
    for (int t = -3; t <= 4; t++) {
        int c = w + t;
        if (c >= 0 && c <= 128) { if (c == 128) c = 126; sy += o[chbase + (size_t)h * 128 + c]; }
    }
    out[idx] = (sx + sy) * 0.125f + loc[idx];
}

// ---------------- depthwise 8x8 conv (pad 3, zero boundary) + BN ----------------
__global__ void dwconv_k(const float* __restrict__ in, const float* __restrict__ w,
                         const float* __restrict__ bng, const float* __restrict__ bnb,
                         float* __restrict__ out)
{
    __shared__ float sIn[23 * 23];
    __shared__ float sWt[64];
    int tile = blockIdx.x;          // 0..63 (8x8 tiles of 16)
    int tX = tile & 7, tY = tile >> 3;
    int c = blockIdx.y, b = blockIdx.z;
    int tid = threadIdx.y * 16 + threadIdx.x;
    if (tid < 64) sWt[tid] = w[c * 64 + tid];
    int h0 = tY * 16 - 3, w0 = tX * 16 - 3;
    const float* ip = in + (size_t)(b * 64 + c) * 16384;
    for (int t = tid; t < 23 * 23; t += 256) {
        int iy = t / 23, ix = t - iy * 23;
        int gy = h0 + iy, gx = w0 + ix;
        sIn[t] = (gy >= 0 && gy < 128 && gx >= 0 && gx < 128) ? ip[(size_t)gy * 128 + gx] : 0.f;
    }
    __syncthreads();
    float acc = 0.f;
#pragma unroll
    for (int i = 0; i < 8; i++)
#pragma unroll
        for (int j = 0; j < 8; j++)
            acc += sIn[(threadIdx.y + i) * 23 + threadIdx.x + j] * sWt[i * 8 + j];
    float v = acc * (bng[c] * BN_SC) + bnb[c];
    out[((size_t)(b * 64 + c) * 128 + tY * 16 + threadIdx.y) * 128 + tX * 16 + threadIdx.x] = v;
}

// ---------------- host ----------------
static dim3 convGrid(int Hout, int Wout, int Cout)
{
    return dim3(((Wout + 15) / 16) * ((Hout + 15) / 16), (Cout + 7) / 8, NB);
}

extern "C" void kernel_launch(void* const* d_in, const int* in_sizes, int n_in,
                              void* d_out, int out_size)
{
    const float* x       = (const float*)d_in[0];
    const float* w_qkv   = (const float*)d_in[1];
    const float* w_l1    = (const float*)d_in[2];
    const float* gl1     = (const float*)d_in[3];
    const float* bl1     = (const float*)d_in[4];
    const float* w_l2    = (const float*)d_in[5];
    const float* gl2     = (const float*)d_in[6];
    const float* bl2     = (const float*)d_in[7];
    const float* f_cos   = (const float*)d_in[8];
    const float* f_sin   = (const float*)d_in[9];
    const float* gb_b1   = (const float*)d_in[10];
    const float* gb_b2   = (const float*)d_in[11];
    const float* gb_w    = (const float*)d_in[12];
    const float* w_post  = (const float*)d_in[13];
    const float* g_postp = (const float*)d_in[14];
    const float* b_postp = (const float*)d_in[15];
    const float* w_gc    = (const float*)d_in[16];
    const float* b_gc    = (const float*)d_in[17];
    const float* w_gc1   = (const float*)d_in[18];
    const float* b_gc1   = (const float*)d_in[19];
    const float* w_gc2   = (const float*)d_in[20];
    const float* b_gc2   = (const float*)d_in[21];
    const float* rpb     = (const float*)d_in[22];
    const float* w_dw    = (const float*)d_in[23];
    const float* g_proj  = (const float*)d_in[24];
    const float* b_proj  = (const float*)d_in[25];
    const float* w_pw    = (const float*)d_in[26];
    const int*   relidx  = (const int*)  d_in[27];
    float* out = (float*)d_out;

    float *loc, *qkv, *obuf, *sum, *dw, *xc, *fft, *xc2, *cr1, *ci1, *cr2, *ci2;
    float *pb, *qb, *rb, *sb, *tb, *ub, *vb, *Cm, *Sm;
    cudaGetSymbolAddress((void**)&loc,  g_local);
    cudaGetSymbolAddress((void**)&qkv,  g_qkv);
    cudaGetSymbolAddress((void**)&obuf, g_o);
    cudaGetSymbolAddress((void**)&sum,  g_sum);
    cudaGetSymbolAddress((void**)&dw,   g_dw);
    cudaGetSymbolAddress((void**)&xc,   g_xc);
    cudaGetSymbolAddress((void**)&fft,  g_fft);
    cudaGetSymbolAddress((void**)&xc2,  g_xc2);
    cudaGetSymbolAddress((void**)&cr1,  g_cr1);
    cudaGetSymbolAddress((void**)&ci1,  g_ci1);
    cudaGetSymbolAddress((void**)&cr2,  g_cr2);
    cudaGetSymbolAddress((void**)&ci2,  g_ci2);
    cudaGetSymbolAddress((void**)&pb,   g_p);
    cudaGetSymbolAddress((void**)&qb,   g_q);
    cudaGetSymbolAddress((void**)&rb,   g_r);
    cudaGetSymbolAddress((void**)&sb,   g_s);
    cudaGetSymbolAddress((void**)&tb,   g_t);
    cudaGetSymbolAddress((void**)&ub,   g_u);
    cudaGetSymbolAddress((void**)&vb,   g_v);
    cudaGetSymbolAddress((void**)&Cm,   g_Cm);
    cudaGetSymbolAddress((void**)&Sm,   g_Sm);

    const int T = 256;
    int nIMG2 = NIMG * NS * NS;
    int nFULL = NB * NC * HW128 * HW128;

    // local pre: bn(conv3x3(x,w_l1)) + bn(conv1x1(x,w_l2))
    conv_k<<<convGrid(128,128,64), T>>>(x, w_l1, nullptr, gl1, bl1, loc,
                                        64,128,128, 64,64,0, 3,1,1, 128,128, 0,0);
    conv_k<<<convGrid(128,128,64), T>>>(x, w_l2, nullptr, gl2, bl2, loc,
                                        64,128,128, 64,64,0, 1,1,0, 128,128, 0,1);
    // gabor cos/sin convs (valid, 128->126), biases
    conv_k<<<convGrid(126,126,32), T>>>(loc, f_cos, gb_b1, nullptr, nullptr, xc,
                                        64,128,128, 32,64,0,  3,1,0, 126,126, 0,0);
    conv_k<<<convGrid(126,126,32), T>>>(loc, f_sin, gb_b2, nullptr, nullptr, xc,
                                        64,128,128, 32,64,32, 3,1,0, 126,126, 0,0);
    // DFT high-pass: fft2 -> mask*|f| -> ifft2 -> abs
    initdft_k<<<(NS*NS + T - 1)/T, T>>>();
    dim3 gg(2, 2, NIMG), bbk(16, 16);
    cgemm_k<<<gg, bbk>>>(Cm, Sm, -1.f, xc,  nullptr, cr1, ci1, 1, 0, 0.f, nullptr);  // Y = F X
    cgemm_k<<<gg, bbk>>>(Cm, Sm, -1.f, cr1, ci1,     cr2, ci2, 0, 0, 0.f, nullptr);  // Z = Y F
    mask_k<<<(nIMG2 + T - 1)/T, T>>>(cr2, ci2, nIMG2);
    cgemm_k<<<gg, bbk>>>(Cm, Sm, +1.f, cr2, ci2,     cr1, ci1, 1, 0, 0.f, nullptr);  // U = F* G
    cgemm_k<<<gg, bbk>>>(Cm, Sm, +1.f, cr1, ci1,     cr2, ci2, 0, 1,
                         1.0f/(126.0f*126.0f), fft);                                  // |U F*|/N^2
    combine_k<<<(nIMG2 + T - 1)/T, T>>>(fft, xc, gb_w, xc2, nIMG2);
    // post conv + bn + relu6
    conv_k<<<convGrid(126,126,64), T>>>(xc2, w_post, nullptr, g_postp, b_postp, pb,
                                        64,126,126, 64,64,0, 3,1,1, 126,126, 2,0);
    mp21_k<<<(NIMG*125*125 + T - 1)/T, T>>>(pb, qb);
    conv_k<<<convGrid(62,62,64), T>>>(qb, w_gc, b_gc, nullptr, nullptr, rb,
                                      64,125,125, 64,64,0, 3,2,0, 62,62, 1,0);
    mp22_k<<<(NIMG*31*31 + T - 1)/T, T>>>(rb, sb);
    resize_k<<<(NIMG*16384 + T - 1)/T, T>>>(sb, tb);
    conv_k<<<convGrid(128,128,64), T>>>(tb, w_gc1, b_gc1, nullptr, nullptr, ub,
                                        64,128,128, 64,64,0, 3,1,1, 128,128, 1,0);
    conv_k<<<convGrid(128,128,64), T>>>(ub, w_gc2, b_gc2, nullptr, nullptr, vb,
                                        64,128,128, 64,64,0, 1,1,0, 128,128, 0,0);
    lsm_k<<<(NB*16384 + T - 1)/T, T>>>(vb, loc);   // local branch output -> loc
    // global branch
    conv_k<<<convGrid(128,128,192), T>>>(x, w_qkv, nullptr, nullptr, nullptr, qkv,
                                         64,128,128, 192,192,0, 1,1,0, 128,128, 0,0);
    attn_k<<<dim3(256, NH_, NB), 64>>>(qkv, rpb, relidx, obuf);
    poolsum_k<<<(nFULL + T - 1)/T, T>>>(obuf, loc, sum);
    dwconv_k<<<dim3(64, 64, NB), dim3(16,16)>>>(sum, w_dw, g_proj, b_proj, dw);
    conv_k<<<convGrid(128,128,64), T>>>(dw, w_pw, nullptr, nullptr, nullptr, out,
                                        64,128,128, 64,64,0, 1,1,0, 128,128, 0,0);
    (void)in_sizes; (void)n_in; (void)out_size;
}

// round 2
// speedup vs baseline: 1.7778x; 1.7778x over previous
#include <cuda_runtime.h>
#include <math.h>
#include <cstddef>

// ---------------- constants ----------------
#define BN_SC 0.9999950000374997f   // 1/sqrt(1+1e-5) as float
#define NB 8
#define NC 64
#define NH_ 8
#define HD_ 8
#define HW128 128
#define NS 126                       // gabor conv valid size
#define NIMG (NB*NC)                 // 512
#define ATTN_SCALE 0.35355339059327373f

// ---------------- scratch (static __device__, no allocs) ----------------
__device__ float g_local[NB*NC*HW128*HW128];
__device__ float g_qkv [NB*3*NC*HW128*HW128];
__device__ float g_o   [NB*NC*HW128*HW128];
__device__ float g_sum [NB*NC*HW128*HW128];
__device__ float g_dw  [NB*NC*HW128*HW128];
__device__ float g_xc  [NIMG*NS*NS];
__device__ float g_fft [NIMG*NS*NS];
__device__ float g_xc2 [NIMG*NS*NS];
__device__ float g_cr1 [NIMG*NS*NS];
__device__ float g_ci1 [NIMG*NS*NS];
__device__ float g_cr2 [NIMG*NS*NS];
__device__ float g_ci2 [NIMG*NS*NS];
__device__ float g_p   [NIMG*NS*NS];
__device__ float g_q   [NIMG*125*125];
__device__ float g_r   [NIMG*62*62];
__device__ float g_s   [NIMG*31*31];
__device__ float g_t   [NB*NC*HW128*HW128];
__device__ float g_u   [NB*NC*HW128*HW128];
__device__ float g_v   [NB*NC*HW128*HW128];
__device__ float g_Cm  [NS*NS];
__device__ float g_Sm  [NS*NS];

// ---------------- register-blocked direct conv ----------------
// 256 threads; 32x32 output tile; each thread: 2x2 spatial x 8 co (32 acc).
// Cin fixed at 64. Weights staged in smem as [ci*K*K + kpos][8] (float4-pair reads).
template<int K, int STRIDE>
__global__ void __launch_bounds__(256)
conv_t(const float* __restrict__ in, const float* __restrict__ w,
       const float* __restrict__ bias, const float* __restrict__ bng,
       const float* __restrict__ bnb, float* __restrict__ out,
       int Hin, int Win, int Cout, int CoutTotal, int coOff,
       int pad, int Hout, int Wout, int act, int accum)
{
    constexpr int KK = K * K;
    constexpr int TS = 32;
    constexpr int SPAN = (TS - 1) * STRIDE + K;   // 34 (3,1) / 32 (1,1) / 65 (3,2)
    constexpr int R = STRIDE + K;                 // per-thread input span
    __shared__ __align__(16) float sIn[SPAN * SPAN];
    __shared__ __align__(16) float sW[64 * KK * 8];

    int tileW = (Wout + TS - 1) / TS;
    int tX = blockIdx.x % tileW, tY = blockIdx.x / tileW;
    int ow0 = tX * TS, oh0 = tY * TS;
    int co0 = blockIdx.y << 3;
    int b   = blockIdx.z;
    int tid = threadIdx.x;
    int ty = tid >> 4, tx = tid & 15;

    // stage weights
    for (int t = tid; t < 64 * KK * 8; t += 256) {
        int row = t >> 3, co = t & 7;
        int ci = row / KK, kp = row - ci * KK;
        sW[t] = (co0 + co < Cout) ? w[(size_t)(co0 + co) * (64 * KK) + ci * KK + kp] : 0.f;
    }

    int ih0 = oh0 * STRIDE - pad, iw0 = ow0 * STRIDE - pad;
    float acc[8][2][2];
#pragma unroll
    for (int co = 0; co < 8; co++)
#pragma unroll
        for (int oy = 0; oy < 2; oy++)
#pragma unroll
            for (int ox = 0; ox < 2; ox++) acc[co][oy][ox] = 0.f;

    const float* inb = in + (size_t)b * 64 * Hin * Win;
    int base = (ty * 2 * STRIDE) * SPAN + tx * 2 * STRIDE;

    for (int ci = 0; ci < 64; ci++) {
        __syncthreads();
        const float* ip = inb + (size_t)ci * Hin * Win;
#pragma unroll 4
        for (int t = tid; t < SPAN * SPAN; t += 256) {
            int iy = t / SPAN, ix = t - iy * SPAN;
            int gy = ih0 + iy, gx = iw0 + ix;
            sIn[t] = (gy >= 0 && gy < Hin && gx >= 0 && gx < Win)
                         ? __ldg(&ip[(size_t)gy * Win + gx]) : 0.f;
        }
        __syncthreads();
        // hoist inputs into registers
        float xin[R][R];
#pragma unroll
        for (int r = 0; r < R; r++)
#pragma unroll
            for (int c = 0; c < R; c++) xin[r][c] = sIn[base + r * SPAN + c];
        const float4* wq = reinterpret_cast<const float4*>(&sW[ci * KK * 8]);
#pragma unroll
        for (int kp = 0; kp < KK; kp++) {
            float4 wa = wq[kp * 2], wb = wq[kp * 2 + 1];
            float wv[8] = {wa.x, wa.y, wa.z, wa.w, wb.x, wb.y, wb.z, wb.w};
            int ky = kp / K, kx = kp - ky * K;
#pragma unroll
            for (int oy = 0; oy < 2; oy++)
#pragma unroll
                for (int ox = 0; ox < 2; ox++) {
                    float xv = xin[oy * STRIDE + ky][ox * STRIDE + kx];
#pragma unroll
                    for (int co = 0; co < 8; co++)
                        acc[co][oy][ox] += xv * wv[co];
                }
        }
    }

    // epilogue
#pragma unroll
    for (int co = 0; co < 8; co++) {
        int gco = co0 + co;
        if (gco >= Cout) break;
        float bi = bias ? bias[gco] : 0.f;
        float sc = 1.f, sh = 0.f;
        if (bng) { sc = bng[gco] * BN_SC; sh = bnb[gco]; }
#pragma unroll
        for (int oy = 0; oy < 2; oy++) {
            int oh = oh0 + ty * 2 + oy;
            if (oh >= Hout) continue;
#pragma unroll
            for (int ox = 0; ox < 2; ox++) {
                int ow = ow0 + tx * 2 + ox;
                if (ow >= Wout) continue;
                float v = acc[co][oy][ox] + bi;
                if (bng) v = v * sc + sh;
                if (act == 1) v = fmaxf(v, 0.f);
                else if (act == 2) v = fminf(fmaxf(v, 0.f), 6.f);
                size_t oidx = (((size_t)b * CoutTotal + coOff + gco) * Hout + oh) * Wout + ow;
                if (accum) out[oidx] += v; else out[oidx] = v;
            }
        }
    }
}

// ---------------- DFT matrices ----------------
__global__ void initdft_k()
{
    int idx = blockIdx.x * blockDim.x + threadIdx.x;
    if (idx >= NS * NS) return;
    int u = idx / NS, h = idx % NS;
    int m = (u * h) % NS;
    float xx = (2.0f * (float)m) / (float)NS;
    g_Cm[idx] = cospif(xx);
    g_Sm[idx] = sinpif(xx);
}

// ---------------- batched complex GEMM (126x126, shared DFT factor) ----------------
__global__ void cgemm_k(const float* __restrict__ Fr, const float* __restrict__ Fi, float fiSign,
                        const float* __restrict__ Xr, const float* __restrict__ Xi,
                        float* __restrict__ Cr, float* __restrict__ Ci,
                        int leftF, int doMag, float magScale, float* __restrict__ Mag)
{
    __shared__ __align__(16) float sAr[8][64], sAi[8][64], sBr[8][64], sBi[8][64];
    size_t off = (size_t)blockIdx.z * (NS * NS);
    int row0 = blockIdx.y * 64, col0 = blockIdx.x * 64;
    int tx = threadIdx.x, ty = threadIdx.y;
    int tid = ty * 16 + tx;
    float aR[4][4], aI[4][4];
#pragma unroll
    for (int r = 0; r < 4; r++)
#pragma unroll
        for (int c = 0; c < 4; c++) { aR[r][c] = 0.f; aI[r][c] = 0.f; }

    for (int k0 = 0; k0 < NS; k0 += 8) {
        for (int t = tid; t < 512; t += 256) {
            int kk = t >> 6, r = t & 63;
            int gk = k0 + kk;
            int gi = row0 + r;
            float ar = 0.f, ai = 0.f;
            if (gi < NS && gk < NS) {
                if (leftF) { ar = Fr[gi * NS + gk]; ai = fiSign * Fi[gi * NS + gk]; }
                else { size_t o = off + (size_t)gi * NS + gk; ar = Xr[o]; ai = Xi ? Xi[o] : 0.f; }
            }
            sAr[kk][r] = ar; sAi[kk][r] = ai;
            int gj = col0 + r;
            float br = 0.f, bi = 0.f;
            if (gj < NS && gk < NS) {
                if (leftF) { size_t o = off + (size_t)gk * NS + gj; br = Xr[o]; bi = Xi ? Xi[o] : 0.f; }
                else { br = Fr[gk * NS + gj]; bi = fiSign * Fi[gk * NS + gj]; }
            }
            sBr[kk][r] = br; sBi[kk][r] = bi;
        }
        __syncthreads();
#pragma unroll
        for (int kk = 0; kk < 8; kk++) {
            float4 a4r = *(const float4*)&sAr[kk][ty * 4];
            float4 a4i = *(const float4*)&sAi[kk][ty * 4];
            float4 b4r = *(const float4*)&sBr[kk][tx * 4];
            float4 b4i = *(const float4*)&sBi[kk][tx * 4];
            float ar[4] = {a4r.x, a4r.y, a4r.z, a4r.w};
            float ai[4] = {a4i.x, a4i.y, a4i.z, a4i.w};
            float br[4] = {b4r.x, b4r.y, b4r.z, b4r.w};
            float bi[4] = {b4i.x, b4i.y, b4i.z, b4i.w};
#pragma unroll
            for (int r = 0; r < 4; r++)
#pragma unroll
                for (int c = 0; c < 4; c++) {
                    aR[r][c] += ar[r] * br[c] - ai[r] * bi[c];
                    aI[r][c] += ar[r] * bi[c] + ai[r] * br[c];
                }
        }
        __syncthreads();
    }
#pragma unroll
    for (int r = 0; r < 4; r++)
#pragma unroll
        for (int c = 0; c < 4; c++) {
            int gi = row0 + ty * 4 + r, gj = col0 + tx * 4 + c;
            if (gi < NS && gj < NS) {
                size_t o = off + (size_t)gi * NS + gj;
                if (doMag) Mag[o] = sqrtf(aR[r][c] * aR[r][c] + aI[r][c] * aI[r][c]) * magScale;
                else { Cr[o] = aR[r][c]; Ci[o] = aI[r][c]; }
            }
        }
}

// ---------------- pointwise: high-pass mask in freq domain ----------------
__global__ void mask_k(float* __restrict__ zr, float* __restrict__ zi, int n)
{
    int idx = blockIdx.x * blockDim.x + threadIdx.x;
    if (idx >= n) return;
    int within = idx % (NS * NS);
    int u = within / NS, v = within % NS;
    int su = (u < 63) ? u : u - NS;
    int sv = (v < 63) ? v : v - NS;
    float r = zr[idx], i = zi[idx];
    float s = (su * su + sv * sv > 1600) ? sqrtf(r * r + i * i) : 0.f;
    zr[idx] = r * s;
    zi[idx] = i * s;
}

// ---------------- combine fft branch with passthrough ----------------
__global__ void combine_k(const float* __restrict__ fft, const float* __restrict__ xc,
                          const float* __restrict__ gbw, float* __restrict__ out, int n)
{
    int idx = blockIdx.x * blockDim.x + threadIdx.x;
    if (idx >= n) return;
    float w0 = fmaxf(gbw[0], 0.f), w1 = fmaxf(gbw[1], 0.f);
    float d = w0 + w1 + 1e-8f;
    out[idx] = (w0 / d) * fft[idx] + (w1 / d) * xc[idx];
}

// ---------------- maxpools ----------------
__global__ void mp21_k(const float* __restrict__ in, float* __restrict__ out)
{
    int idx = blockIdx.x * blockDim.x + threadIdx.x;
    int n = NIMG * 125 * 125;
    if (idx >= n) return;
    int w = idx % 125, h = (idx / 125) % 125, ch = idx / (125 * 125);
    const float* p = in + (size_t)ch * NS * NS + (size_t)h * NS + w;
    out[idx] = fmaxf(fmaxf(p[0], p[1]), fmaxf(p[NS], p[NS + 1]));
}
__global__ void mp22_k(const float* __restrict__ in, float* __restrict__ out)
{
    int idx = blockIdx.x * blockDim.x + threadIdx.x;
    int n = NIMG * 31 * 31;
    if (idx >= n) return;
    int w = idx % 31, h = (idx / 31) % 31, ch = idx / (31 * 31);
    const float* p = in + (size_t)ch * 62 * 62 + (size_t)(2 * h) * 62 + 2 * w;
    out[idx] = fmaxf(fmaxf(p[0], p[1]), fmaxf(p[62], p[63]));
}

// ---------------- bilinear resize 31 -> 128 ----------------
__global__ void resize_k(const float* __restrict__ in, float* __restrict__ out)
{
    int idx = blockIdx.x * blockDim.x + threadIdx.x;
    int n = NIMG * HW128 * HW128;
    if (idx >= n) return;
    int x = idx & 127, y = (idx >> 7) & 127, ch = idx >> 14;
    const float sc = 31.f / 128.f;
    float sy = fminf(fmaxf((y + 0.5f) * sc - 0.5f, 0.f), 30.f);
    float sx = fminf(fmaxf((x + 0.5f) * sc - 0.5f, 0.f), 30.f);
    int y0 = (int)floorf(sy); float fy = sy - y0; int y1 = min(y0 + 1, 30);
    int x0 = (int)floorf(sx); float fx = sx - x0; int x1 = min(x0 + 1, 30);
    const float* p = in + (size_t)ch * 961;
    float v = (1.f - fy) * ((1.f - fx) * p[y0 * 31 + x0] + fx * p[y0 * 31 + x1])
            + fy         * ((1.f - fx) * p[y1 * 31 + x0] + fx * p[y1 * 31 + x1]);
    out[idx] = v;
}

// ---------------- log_softmax over channels ----------------
__global__ void lsm_k(const float* __restrict__ in, float* __restrict__ out)
{
    int gid = blockIdx.x * blockDim.x + threadIdx.x;
    if (gid >= NB * HW128 * HW128) return;
    int b = gid >> 14, p = gid & 16383;
    size_t base = (size_t)b * NC * 16384 + p;
    float mx = -1e30f;
    for (int c = 0; c < NC; c++) mx = fmaxf(mx, in[base + (size_t)c * 16384]);
    float s = 0.f;
    for (int c = 0; c < NC; c++) s += expf(in[base + (size_t)c * 16384] - mx);
    float l = logf(s);
    for (int c = 0; c < NC; c++) {
        size_t o = base + (size_t)c * 16384;
        out[o] = in[o] - mx - l;
    }
}

// ---------------- windowed attention ----------------
__global__ void attn_k(const float* __restrict__ qkv, const float* __restrict__ rpb,
                       const int* __restrict__ relidx, float* __restrict__ o)
{
    __shared__ float sk[64][8];
    __shared__ float sv[64][8];
    int win = blockIdx.x;            // 0..255
    int gh = win >> 4, gw = win & 15;
    int n = blockIdx.y, b = blockIdx.z;
    int i = threadIdx.x;             // token 0..63
    int hi = gh * 8 + (i >> 3), wi = gw * 8 + (i & 7);
    float q[8];
#pragma unroll
    for (int d = 0; d < 8; d++) {
        int cq = n * 8 + d;
        size_t sp = (size_t)hi * 128 + wi;
        q[d]      = qkv[(((size_t)b * 192 + cq)       * 16384) + sp];
        sk[i][d]  = qkv[(((size_t)b * 192 + 64 + cq)  * 16384) + sp];
        sv[i][d]  = qkv[(((size_t)b * 192 + 128 + cq) * 16384) + sp];
    }
    __syncthreads();
    float logits[64];
    float mx = -1e30f;
#pragma unroll
    for (int j = 0; j < 64; j++) {
        float dot = 0.f;
#pragma unroll
        for (int d = 0; d < 8; d++) dot += q[d] * sk[j][d];
        float l = dot * ATTN_SCALE + rpb[relidx[i * 64 + j] * 8 + n];
        logits[j] = l;
        mx = fmaxf(mx, l);
    }
    float se = 0.f;
#pragma unroll
    for (int j = 0; j < 64; j++) { float e = expf(logits[j] - mx); logits[j] = e; se += e; }
    float inv = 1.f / se;
    float od[8];
#pragma unroll
    for (int d = 0; d < 8; d++) od[d] = 0.f;
#pragma unroll
    for (int j = 0; j < 64; j++) {
#pragma unroll
        for (int d = 0; d < 8; d++) od[d] += logits[j] * sv[j][d];
    }
#pragma unroll
    for (int d = 0; d < 8; d++)
        o[(((size_t)b * 64 + n * 8 + d) * 128 + hi) * 128 + wi] = od[d] * inv;
}

// ---------------- directional pools + add local ----------------
__global__ void poolsum_k(const float* __restrict__ o, const float* __restrict__ loc,
                          float* __restrict__ out)
{
    int idx = blockIdx.x * blockDim.x + threadIdx.x;
    int n = NB * NC * HW128 * HW128;
    if (idx >= n) return;
    int w = idx & 127, h = (idx >> 7) & 127;
    size_t chbase = (size_t)(idx >> 14) * 16384;
    float sx = 0.f;
#pragma unroll
    for (int t = -3; t <= 4; t++) {
        int r = h + t;
        if (r >= 0 && r <= 128) { if (r == 128) r = 126; sx += o[chbase + (size_t)r * 128 + w]; }
    }
    float sy = 0.f;
#pragma unroll
    for (int t = -3; t <= 4; t++) {
        int c = w + t;
        if (c >= 0 && c <= 128) { if (c == 128) c = 126; sy += o[chbase + (size_t)h * 128 + c]; }
    }
    out[idx] = (sx + sy) * 0.125f + loc[idx];
}

// ---------------- depthwise 8x8 conv (pad 3, zero boundary) + BN ----------------
__global__ void dwconv_k(const float* __restrict__ in, const float* __restrict__ w,
                         const float* __restrict__ bng, const float* __restrict__ bnb,
                         float* __restrict__ out)
{
    __shared__ float sIn[23 * 23];
    __shared__ float sWt[64];
    int tile = blockIdx.x;          // 0..63 (8x8 tiles of 16)
    int tX = tile & 7, tY = tile >> 3;
    int c = blockIdx.y, b = blockIdx.z;
    int tid = threadIdx.y * 16 + threadIdx.x;
    if (tid < 64) sWt[tid] = w[c * 64 + tid];
    int h0 = tY * 16 - 3, w0 = tX * 16 - 3;
    const float* ip = in + (size_t)(b * 64 + c) * 16384;
    for (int t = tid; t < 23 * 23; t += 256) {
        int iy = t / 23, ix = t - iy * 23;
        int gy = h0 + iy, gx = w0 + ix;
        sIn[t] = (gy >= 0 && gy < 128 && gx >= 0 && gx < 128) ? ip[(size_t)gy * 128 + gx] : 0.f;
    }
    __syncthreads();
    float acc = 0.f;
#pragma unroll
    for (int i = 0; i < 8; i++)
#pragma unroll
        for (int j = 0; j < 8; j++)
            acc += sIn[(threadIdx.y + i) * 23 + threadIdx.x + j] * sWt[i * 8 + j];
    float v = acc * (bng[c] * BN_SC) + bnb[c];
    out[((size_t)(b * 64 + c) * 128 + tY * 16 + threadIdx.y) * 128 + tX * 16 + threadIdx.x] = v;
}

// ---------------- host ----------------
static dim3 convGridT(int Hout, int Wout, int Cout)
{
    return dim3(((Wout + 31) / 32) * ((Hout + 31) / 32), (Cout + 7) / 8, NB);
}

extern "C" void kernel_launch(void* const* d_in, const int* in_sizes, int n_in,
                              void* d_out, int out_size)
{
    const float* x       = (const float*)d_in[0];
    const float* w_qkv   = (const float*)d_in[1];
    const float* w_l1    = (const float*)d_in[2];
    const float* gl1     = (const float*)d_in[3];
    const float* bl1     = (const float*)d_in[4];
    const float* w_l2    = (const float*)d_in[5];
    const float* gl2     = (const float*)d_in[6];
    const float* bl2     = (const float*)d_in[7];
    const float* f_cos   = (const float*)d_in[8];
    const float* f_sin   = (const float*)d_in[9];
    const float* gb_b1   = (const float*)d_in[10];
    const float* gb_b2   = (const float*)d_in[11];
    const float* gb_w    = (const float*)d_in[12];
    const float* w_post  = (const float*)d_in[13];
    const float* g_postp = (const float*)d_in[14];
    const float* b_postp = (const float*)d_in[15];
    const float* w_gc    = (const float*)d_in[16];
    const float* b_gc    = (const float*)d_in[17];
    const float* w_gc1   = (const float*)d_in[18];
    const float* b_gc1   = (const float*)d_in[19];
    const float* w_gc2   = (const float*)d_in[20];
    const float* b_gc2   = (const float*)d_in[21];
    const float* rpb     = (const float*)d_in[22];
    const float* w_dw    = (const float*)d_in[23];
    const float* g_proj  = (const float*)d_in[24];
    const float* b_proj  = (const float*)d_in[25];
    const float* w_pw    = (const float*)d_in[26];
    const int*   relidx  = (const int*)  d_in[27];
    float* out = (float*)d_out;

    float *loc, *qkv, *obuf, *sum, *dw, *xc, *fft, *xc2, *cr1, *ci1, *cr2, *ci2;
    float *pb, *qb, *rb, *sb, *tb, *ub, *vb, *Cm, *Sm;
    cudaGetSymbolAddress((void**)&loc,  g_local);
    cudaGetSymbolAddress((void**)&qkv,  g_qkv);
    cudaGetSymbolAddress((void**)&obuf, g_o);
    cudaGetSymbolAddress((void**)&sum,  g_sum);
    cudaGetSymbolAddress((void**)&dw,   g_dw);
    cudaGetSymbolAddress((void**)&xc,   g_xc);
    cudaGetSymbolAddress((void**)&fft,  g_fft);
    cudaGetSymbolAddress((void**)&xc2,  g_xc2);
    cudaGetSymbolAddress((void**)&cr1,  g_cr1);
    cudaGetSymbolAddress((void**)&ci1,  g_ci1);
    cudaGetSymbolAddress((void**)&cr2,  g_cr2);
    cudaGetSymbolAddress((void**)&ci2,  g_ci2);
    cudaGetSymbolAddress((void**)&pb,   g_p);
    cudaGetSymbolAddress((void**)&qb,   g_q);
    cudaGetSymbolAddress((void**)&rb,   g_r);
    cudaGetSymbolAddress((void**)&sb,   g_s);
    cudaGetSymbolAddress((void**)&tb,   g_t);
    cudaGetSymbolAddress((void**)&ub,   g_u);
    cudaGetSymbolAddress((void**)&vb,   g_v);
    cudaGetSymbolAddress((void**)&Cm,   g_Cm);
    cudaGetSymbolAddress((void**)&Sm,   g_Sm);

    const int T = 256;
    int nIMG2 = NIMG * NS * NS;
    int nFULL = NB * NC * HW128 * HW128;

    // local pre: bn(conv3x3(x,w_l1)) + bn(conv1x1(x,w_l2))
    conv_t<3,1><<<convGridT(128,128,64), T>>>(x, w_l1, nullptr, gl1, bl1, loc,
                                              128,128, 64,64,0, 1, 128,128, 0,0);
    conv_t<1,1><<<convGridT(128,128,64), T>>>(x, w_l2, nullptr, gl2, bl2, loc,
                                              128,128, 64,64,0, 0, 128,128, 0,1);
    // gabor cos/sin convs (valid, 128->126)
    conv_t<3,1><<<convGridT(126,126,32), T>>>(loc, f_cos, gb_b1, nullptr, nullptr, xc,
                                              128,128, 32,64,0,  0, 126,126, 0,0);
    conv_t<3,1><<<convGridT(126,126,32), T>>>(loc, f_sin, gb_b2, nullptr, nullptr, xc,
                                              128,128, 32,64,32, 0, 126,126, 0,0);
    // DFT high-pass: fft2 -> mask*|f| -> ifft2 -> abs
    initdft_k<<<(NS*NS + T - 1)/T, T>>>();
    dim3 gg(2, 2, NIMG), bbk(16, 16);
    cgemm_k<<<gg, bbk>>>(Cm, Sm, -1.f, xc,  nullptr, cr1, ci1, 1, 0, 0.f, nullptr);  // Y = F X
    cgemm_k<<<gg, bbk>>>(Cm, Sm, -1.f, cr1, ci1,     cr2, ci2, 0, 0, 0.f, nullptr);  // Z = Y F
    mask_k<<<(nIMG2 + T - 1)/T, T>>>(cr2, ci2, nIMG2);
    cgemm_k<<<gg, bbk>>>(Cm, Sm, +1.f, cr2, ci2,     cr1, ci1, 1, 0, 0.f, nullptr);  // U = F* G
    cgemm_k<<<gg, bbk>>>(Cm, Sm, +1.f, cr1, ci1,     cr2, ci2, 0, 1,
                         1.0f/(126.0f*126.0f), fft);                                  // |U F*|/N^2
    combine_k<<<(nIMG2 + T - 1)/T, T>>>(fft, xc, gb_w, xc2, nIMG2);
    // post conv + bn + relu6
    conv_t<3,1><<<convGridT(126,126,64), T>>>(xc2, w_post, nullptr, g_postp, b_postp, pb,
                                              126,126, 64,64,0, 1, 126,126, 2,0);
    mp21_k<<<(NIMG*125*125 + T - 1)/T, T>>>(pb, qb);
    conv_t<3,2><<<convGridT(62,62,64), T>>>(qb, w_gc, b_gc, nullptr, nullptr, rb,
                                            125,125, 64,64,0, 0, 62,62, 1,0);
    mp22_k<<<(NIMG*31*31 + T - 1)/T, T>>>(rb, sb);
    resize_k<<<(NIMG*16384 + T - 1)/T, T>>>(sb, tb);
    conv_t<3,1><<<convGridT(128,128,64), T>>>(tb, w_gc1, b_gc1, nullptr, nullptr, ub,
                                              128,128, 64,64,0, 1, 128,128, 1,0);
    conv_t<1,1><<<convGridT(128,128,64), T>>>(ub, w_gc2, b_gc2, nullptr, nullptr, vb,
                                              128,128, 64,64,0, 0, 128,128, 0,0);
    lsm_k<<<(NB*16384 + T - 1)/T, T>>>(vb, loc);   // local branch output -> loc
    // global branch
    conv_t<1,1><<<convGridT(128,128,192), T>>>(x, w_qkv, nullptr, nullptr, nullptr, qkv,
                                               128,128, 192,192,0, 0, 128,128, 0,0);
    attn_k<<<dim3(256, NH_, NB), 64>>>(qkv, rpb, relidx, obuf);
    poolsum_k<<<(nFULL + T - 1)/T, T>>>(obuf, loc, sum);
    dwconv_k<<<dim3(64, 64, NB), dim3(16,16)>>>(sum, w_dw, g_proj, b_proj, dw);
    conv_t<1,1><<<convGridT(128,128,64), T>>>(dw, w_pw, nullptr, nullptr, nullptr, out,
                                              128,128, 64,64,0, 0, 128,128, 0,0);
    (void)in_sizes; (void)n_in; (void)out_size;
}

// round 3
// speedup vs baseline: 2.0873x; 1.1741x over previous
#include <cuda_runtime.h>
#include <math.h>
#include <cstddef>

// ---------------- constants ----------------
#define BN_SC 0.9999950000374997f   // 1/sqrt(1+1e-5) as float
#define NB 8
#define NC 64
#define NH_ 8
#define HW128 128
#define NS 126                       // gabor conv valid size
#define NIMG (NB*NC)                 // 512
#define ATTN_SCALE 0.35355339059327373f

// ---------------- scratch (static __device__, no allocs) ----------------
__device__ float g_local[NB*NC*HW128*HW128];
__device__ float g_qkv [NB*3*NC*HW128*HW128];
__device__ float g_o   [NB*NC*HW128*HW128];
__device__ float g_sum [NB*NC*HW128*HW128];
__device__ float g_dw  [NB*NC*HW128*HW128];
__device__ float g_xc  [NIMG*NS*NS];
__device__ float g_xc2 [NIMG*NS*NS];
__device__ float g_cr1 [NIMG*NS*NS];
__device__ float g_ci1 [NIMG*NS*NS];
__device__ float g_cr2 [NIMG*NS*NS];
__device__ float g_ci2 [NIMG*NS*NS];
__device__ float g_p   [NIMG*NS*NS];
__device__ float g_q   [NIMG*125*125];
__device__ float g_r   [NIMG*62*62];
__device__ float g_s   [NIMG*31*31];
__device__ float g_t   [NB*NC*HW128*HW128];
__device__ float g_u   [NB*NC*HW128*HW128];
__device__ float g_v   [NB*NC*HW128*HW128];
__device__ float g_Cm  [NS*NS];
__device__ float g_Sm  [NS*NS];
__device__ float g_wl  [64*64*9];
__device__ float g_bl  [64];
__device__ float g_wgab[64*64*9];
__device__ float g_bgab[64];

// ---------------- weight-prep kernels ----------------
__global__ void prep_l_k(const float* __restrict__ w1, const float* __restrict__ gg1,
                         const float* __restrict__ bb1, const float* __restrict__ w2,
                         const float* __restrict__ gg2, const float* __restrict__ bb2)
{
    int idx = blockIdx.x * blockDim.x + threadIdx.x;
    if (idx < 64*64*9) {
        int co = idx / (64*9);
        int rem = idx - co * (64*9);
        int ci = rem / 9, k = rem - ci * 9;
        float v = w1[idx] * (gg1[co] * BN_SC);
        if (k == 4) v += w2[co*64 + ci] * (gg2[co] * BN_SC);
        g_wl[idx] = v;
    }
    if (idx < 64) g_bl[idx] = bb1[idx] + bb2[idx];
}

__global__ void prep_gab_k(const float* __restrict__ fc, const float* __restrict__ fs,
                           const float* __restrict__ bc, const float* __restrict__ bs)
{
    int idx = blockIdx.x * blockDim.x + threadIdx.x;
    if (idx < 64*64*9) {
        int co = idx / (64*9);
        g_wgab[idx] = (co < 32) ? fc[idx] : fs[idx - 32*64*9];
    }
    if (idx < 64) g_bgab[idx] = (idx < 32) ? bc[idx] : bs[idx - 32];
}

// ---------------- register-blocked direct conv ----------------
// 256 threads; 32x32 output tile; each thread: 2x2 spatial x 8 co.
// STRIDE==1 path: double-buffered smem with reg prefetch, float2 LDS.
template<int K, int STRIDE>
__global__ void __launch_bounds__(256)
conv_t(const float* __restrict__ in, const float* __restrict__ w,
       const float* __restrict__ bias, const float* __restrict__ bng,
       const float* __restrict__ bnb, float* __restrict__ out,
       int Hin, int Win, int Cout, int CoutTotal, int coOff,
       int pad, int Hout, int Wout, int act, int accum)
{
    constexpr int KK = K * K;
    constexpr int TS = 32;
    constexpr int SPAN = (TS - 1) * STRIDE + K;
    constexpr int R = STRIDE + K;
    __shared__ __align__(16) float sW[64 * KK * 8];

    int tileW = (Wout + TS - 1) / TS;
    int tX = blockIdx.x % tileW, tY = blockIdx.x / tileW;
    int ow0 = tX * TS, oh0 = tY * TS;
    int co0 = blockIdx.y << 3;
    int b   = blockIdx.z;
    int tid = threadIdx.x;
    int ty = tid >> 4, tx = tid & 15;

    for (int t = tid; t < 64 * KK * 8; t += 256) {
        int row = t >> 3, co = t & 7;
        int ci = row / KK, kp = row - ci * KK;
        sW[t] = (co0 + co < Cout) ? w[(size_t)(co0 + co) * (64 * KK) + ci * KK + kp] : 0.f;
    }

    int ih0 = oh0 * STRIDE - pad, iw0 = ow0 * STRIDE - pad;
    float acc[8][2][2];
#pragma unroll
    for (int co = 0; co < 8; co++)
#pragma unroll
        for (int oy = 0; oy < 2; oy++)
#pragma unroll
            for (int ox = 0; ox < 2; ox++) acc[co][oy][ox] = 0.f;

    const float* inb = in + (size_t)b * 64 * Hin * Win;
    int base = (ty * 2 * STRIDE) * SPAN + tx * 2 * STRIDE;

    if constexpr (STRIDE == 1) {
        constexpr int NLD = (SPAN * SPAN + 255) / 256;
        __shared__ __align__(16) float sIn[2][SPAN * SPAN];
        float rld[NLD];
        auto prefetch = [&](int ci) {
#pragma unroll
            for (int j = 0; j < NLD; j++) {
                int t = tid + j * 256;
                float v = 0.f;
                if (t < SPAN * SPAN) {
                    int iy = t / SPAN, ix = t - iy * SPAN;
                    int gy = ih0 + iy, gx = iw0 + ix;
                    if (gy >= 0 && gy < Hin && gx >= 0 && gx < Win)
                        v = __ldg(&inb[(size_t)ci * Hin * Win + (size_t)gy * Win + gx]);
                }
                rld[j] = v;
            }
        };
        prefetch(0);
        for (int ci = 0; ci < 64; ci++) {
            float* sb = sIn[ci & 1];
#pragma unroll
            for (int j = 0; j < NLD; j++) {
                int t = tid + j * 256;
                if (t < SPAN * SPAN) sb[t] = rld[j];
            }
            __syncthreads();
            if (ci < 63) prefetch(ci + 1);
            // float2 loads of the RxR per-thread input patch
            float xin[R][R];
            const float2* s2 = reinterpret_cast<const float2*>(sb);
            int b2 = base >> 1;
#pragma unroll
            for (int r = 0; r < R; r++)
#pragma unroll
                for (int c = 0; c < R / 2; c++) {
                    float2 v = s2[b2 + r * (SPAN / 2) + c];
                    xin[r][2 * c] = v.x; xin[r][2 * c + 1] = v.y;
                }
            const float4* wq = reinterpret_cast<const float4*>(&sW[ci * KK * 8]);
#pragma unroll
            for (int kp = 0; kp < KK; kp++) {
                float4 wa = wq[kp * 2], wb = wq[kp * 2 + 1];
                float wv[8] = {wa.x, wa.y, wa.z, wa.w, wb.x, wb.y, wb.z, wb.w};
                int ky = kp / K, kx = kp - ky * K;
#pragma unroll
                for (int oy = 0; oy < 2; oy++)
#pragma unroll
                    for (int ox = 0; ox < 2; ox++) {
                        float xv = xin[oy + ky][ox + kx];
#pragma unroll
                        for (int co = 0; co < 8; co++)
                            acc[co][oy][ox] += xv * wv[co];
                    }
            }
        }
    } else {
        __shared__ float sIn1[SPAN * SPAN];
        for (int ci = 0; ci < 64; ci++) {
            __syncthreads();
            const float* ip = inb + (size_t)ci * Hin * Win;
            for (int t = tid; t < SPAN * SPAN; t += 256) {
                int iy = t / SPAN, ix = t - iy * SPAN;
                int gy = ih0 + iy, gx = iw0 + ix;
                sIn1[t] = (gy >= 0 && gy < Hin && gx >= 0 && gx < Win)
                              ? __ldg(&ip[(size_t)gy * Win + gx]) : 0.f;
            }
            __syncthreads();
            float xin[R][R];
#pragma unroll
            for (int r = 0; r < R; r++)
#pragma unroll
                for (int c = 0; c < R; c++) xin[r][c] = sIn1[base + r * SPAN + c];
            const float4* wq = reinterpret_cast<const float4*>(&sW[ci * KK * 8]);
#pragma unroll
            for (int kp = 0; kp < KK; kp++) {
                float4 wa = wq[kp * 2], wb = wq[kp * 2 + 1];
                float wv[8] = {wa.x, wa.y, wa.z, wa.w, wb.x, wb.y, wb.z, wb.w};
                int ky = kp / K, kx = kp - ky * K;
#pragma unroll
                for (int oy = 0; oy < 2; oy++)
#pragma unroll
                    for (int ox = 0; ox < 2; ox++) {
                        float xv = xin[oy * STRIDE + ky][ox * STRIDE + kx];
#pragma unroll
                        for (int co = 0; co < 8; co++)
                            acc[co][oy][ox] += xv * wv[co];
                    }
            }
        }
    }

    // epilogue
#pragma unroll
    for (int co = 0; co < 8; co++) {
        int gco = co0 + co;
        if (gco >= Cout) break;
        float bi = bias ? bias[gco] : 0.f;
        float sc = 1.f, sh = 0.f;
        if (bng) { sc = bng[gco] * BN_SC; sh = bnb[gco]; }
#pragma unroll
        for (int oy = 0; oy < 2; oy++) {
            int oh = oh0 + ty * 2 + oy;
            if (oh >= Hout) continue;
#pragma unroll
            for (int ox = 0; ox < 2; ox++) {
                int ow = ow0 + tx * 2 + ox;
                if (ow >= Wout) continue;
                float v = acc[co][oy][ox] + bi;
                if (bng) v = v * sc + sh;
                if (act == 1) v = fmaxf(v, 0.f);
                else if (act == 2) v = fminf(fmaxf(v, 0.f), 6.f);
                size_t oidx = (((size_t)b * CoutTotal + coOff + gco) * Hout + oh) * Wout + ow;
                if (accum) out[oidx] += v; else out[oidx] = v;
            }
        }
    }
}

// ---------------- DFT matrices ----------------
__global__ void initdft_k()
{
    int idx = blockIdx.x * blockDim.x + threadIdx.x;
    if (idx >= NS * NS) return;
    int u = idx / NS, h = idx % NS;
    int m = (u * h) % NS;
    float xx = (2.0f * (float)m) / (float)NS;
    g_Cm[idx] = cospif(xx);
    g_Sm[idx] = sinpif(xx);
}

// ---------------- DFT GEMM stages ----------------
// MODE 1: C = F X          (X real;  F = Cm - i Sm)     -> (Cr, Ci)
// MODE 2: Z = Y F          (full complex) + mask epi    -> (Cr, Ci)
// MODE 3: U = F* G         (full complex; F* = Cm+iSm)  -> (Cr, Ci)
// MODE 4: W = Re(U F*)     + |.|/N^2 + combine epi      -> outbuf
template<int MODE>
__global__ void __launch_bounds__(256)
cgemm_t(const float* __restrict__ Xr, const float* __restrict__ Xi,
        float* __restrict__ Cr, float* __restrict__ Ci,
        const float* __restrict__ xcIn, const float* __restrict__ gbw,
        float* __restrict__ outbuf)
{
    __shared__ __align__(16) float sAr[8][64], sAi[8][64], sBr[8][64], sBi[8][64];
    size_t off = (size_t)blockIdx.z * (NS * NS);
    int row0 = blockIdx.y * 64, col0 = blockIdx.x * 64;
    int tx = threadIdx.x, ty = threadIdx.y;
    int tid = ty * 16 + tx;
    float aR[4][4], aI[4][4];
#pragma unroll
    for (int r = 0; r < 4; r++)
#pragma unroll
        for (int c = 0; c < 4; c++) { aR[r][c] = 0.f; aI[r][c] = 0.f; }

    for (int k0 = 0; k0 < NS; k0 += 8) {
        for (int t = tid; t < 512; t += 256) {
            int kk = t >> 6, r = t & 63;
            int gk = k0 + kk;
            int gi = row0 + r;
            float ar = 0.f, ai = 0.f;
            if (gi < NS && gk < NS) {
                if constexpr (MODE == 1 || MODE == 3) {
                    ar = g_Cm[gi * NS + gk];
                    ai = (MODE == 1) ? -g_Sm[gi * NS + gk] : g_Sm[gi * NS + gk];
                } else {
                    size_t o = off + (size_t)gi * NS + gk;
                    ar = Xr[o]; ai = Xi[o];
                }
            }
            sAr[kk][r] = ar; sAi[kk][r] = ai;
            int gj = col0 + r;
            float br = 0.f, bi = 0.f;
            if (gj < NS && gk < NS) {
                if constexpr (MODE == 1) {
                    br = Xr[off + (size_t)gk * NS + gj];
                } else if constexpr (MODE == 3) {
                    size_t o = off + (size_t)gk * NS + gj;
                    br = Xr[o]; bi = Xi[o];
                } else {
                    br = g_Cm[gk * NS + gj];
                    bi = (MODE == 2) ? -g_Sm[gk * NS + gj] : g_Sm[gk * NS + gj];
                }
            }
            sBr[kk][r] = br;
            if constexpr (MODE != 1) sBi[kk][r] = bi;
        }
        __syncthreads();
#pragma unroll
        for (int kk = 0; kk < 8; kk++) {
            float4 a4r = *(const float4*)&sAr[kk][ty * 4];
            float4 a4i = *(const float4*)&sAi[kk][ty * 4];
            float4 b4r = *(const float4*)&sBr[kk][tx * 4];
            float ar[4] = {a4r.x, a4r.y, a4r.z, a4r.w};
            float ai[4] = {a4i.x, a4i.y, a4i.z, a4i.w};
            float br[4] = {b4r.x, b4r.y, b4r.z, b4r.w};
            if constexpr (MODE == 1) {
#pragma unroll
                for (int r = 0; r < 4; r++)
#pragma unroll
                    for (int c = 0; c < 4; c++) {
                        aR[r][c] += ar[r] * br[c];
                        aI[r][c] += ai[r] * br[c];
                    }
            } else {
                float4 b4i = *(const float4*)&sBi[kk][tx * 4];
                float bi[4] = {b4i.x, b4i.y, b4i.z, b4i.w};
                if constexpr (MODE == 4) {
#pragma unroll
                    for (int r = 0; r < 4; r++)
#pragma unroll
                        for (int c = 0; c < 4; c++)
                            aR[r][c] += ar[r] * br[c] - ai[r] * bi[c];
                } else {
#pragma unroll
                    for (int r = 0; r < 4; r++)
#pragma unroll
                        for (int c = 0; c < 4; c++) {
                            aR[r][c] += ar[r] * br[c] - ai[r] * bi[c];
                            aI[r][c] += ar[r] * bi[c] + ai[r] * br[c];
                        }
                }
            }
        }
        __syncthreads();
    }

    float fw0 = 0.f, fw1 = 0.f;
    if constexpr (MODE == 4) {
        float w0 = fmaxf(gbw[0], 0.f), w1 = fmaxf(gbw[1], 0.f);
        float d = w0 + w1 + 1e-8f;
        fw0 = (w0 / d) * (1.0f / (126.0f * 126.0f));
        fw1 = w1 / d;
    }
#pragma unroll
    for (int r = 0; r < 4; r++)
#pragma unroll
        for (int c = 0; c < 4; c++) {
            int gi = row0 + ty * 4 + r, gj = col0 + tx * 4 + c;
            if (gi < NS && gj < NS) {
                size_t o = off + (size_t)gi * NS + gj;
                if constexpr (MODE == 2) {
                    int su = (gi < 63) ? gi : gi - NS;
                    int sv = (gj < 63) ? gj : gj - NS;
                    float rr = aR[r][c], ii = aI[r][c];
                    float s = (su * su + sv * sv > 1600)
                                  ? sqrtf(rr * rr + ii * ii) : 0.f;
                    Cr[o] = rr * s; Ci[o] = ii * s;
                } else if constexpr (MODE == 4) {
                    outbuf[o] = fw0 * fabsf(aR[r][c]) + fw1 * xcIn[o];
                } else {
                    Cr[o] = aR[r][c]; Ci[o] = aI[r][c];
                }
            }
        }
}

// ---------------- maxpools ----------------
__global__ void mp21_k(const float* __restrict__ in, float* __restrict__ out)
{
    int idx = blockIdx.x * blockDim.x + threadIdx.x;
    int n = NIMG * 125 * 125;
    if (idx >= n) return;
    int w = idx % 125, h = (idx / 125) % 125, ch = idx / (125 * 125);
    const float* p = in + (size_t)ch * NS * NS + (size_t)h * NS + w;
    out[idx] = fmaxf(fmaxf(p[0], p[1]), fmaxf(p[NS], p[NS + 1]));
}
__global__ void mp22_k(const float* __restrict__ in, float* __restrict__ out)
{
    int idx = blockIdx.x * blockDim.x + threadIdx.x;
    int n = NIMG * 31 * 31;
    if (idx >= n) return;
    int w = idx % 31, h = (idx / 31) % 31, ch = idx / (31 * 31);
    const float* p = in + (size_t)ch * 62 * 62 + (size_t)(2 * h) * 62 + 2 * w;
    out[idx] = fmaxf(fmaxf(p[0], p[1]), fmaxf(p[62], p[63]));
}

// ---------------- bilinear resize 31 -> 128 ----------------
__global__ void resize_k(const float* __restrict__ in, float* __restrict__ out)
{
    int idx = blockIdx.x * blockDim.x + threadIdx.x;
    int n = NIMG * HW128 * HW128;
    if (idx >= n) return;
    int x = idx & 127, y = (idx >> 7) & 127, ch = idx >> 14;
    const float sc = 31.f / 128.f;
    float sy = fminf(fmaxf((y + 0.5f) * sc - 0.5f, 0.f), 30.f);
    float sx = fminf(fmaxf((x + 0.5f) * sc - 0.5f, 0.f), 30.f);
    int y0 = (int)floorf(sy); float fy = sy - y0; int y1 = min(y0 + 1, 30);
    int x0 = (int)floorf(sx); float fx = sx - x0; int x1 = min(x0 + 1, 30);
    const float* p = in + (size_t)ch * 961;
    float v = (1.f - fy) * ((1.f - fx) * p[y0 * 31 + x0] + fx * p[y0 * 31 + x1])
            + fy         * ((1.f - fx) * p[y1 * 31 + x0] + fx * p[y1 * 31 + x1]);
    out[idx] = v;
}

// ---------------- log_softmax over channels ----------------
__global__ void lsm_k(const float* __restrict__ in, float* __restrict__ out)
{
    int gid = blockIdx.x * blockDim.x + threadIdx.x;
    if (gid >= NB * HW128 * HW128) return;
    int b = gid >> 14, p = gid & 16383;
    size_t base = (size_t)b * NC * 16384 + p;
    float mx = -1e30f;
    for (int c = 0; c < NC; c++) mx = fmaxf(mx, in[base + (size_t)c * 16384]);
    float s = 0.f;
    for (int c = 0; c < NC; c++) s += expf(in[base + (size_t)c * 16384] - mx);
    float l = logf(s);
    for (int c = 0; c < NC; c++) {
        size_t o = base + (size_t)c * 16384;
        out[o] = in[o] - mx - l;
    }
}

// ---------------- windowed attention ----------------
__global__ void attn_k(const float* __restrict__ qkv, const float* __restrict__ rpb,
                       const int* __restrict__ relidx, float* __restrict__ o)
{
    __shared__ float sk[64][8];
    __shared__ float sv[64][8];
    int win = blockIdx.x;
    int gh = win >> 4, gw = win & 15;
    int n = blockIdx.y, b = blockIdx.z;
    int i = threadIdx.x;
    int hi = gh * 8 + (i >> 3), wi = gw * 8 + (i & 7);
    float q[8];
#pragma unroll
    for (int d = 0; d < 8; d++) {
        int cq = n * 8 + d;
        size_t sp = (size_t)hi * 128 + wi;
        q[d]      = qkv[(((size_t)b * 192 + cq)       * 16384) + sp];
        sk[i][d]  = qkv[(((size_t)b * 192 + 64 + cq)  * 16384) + sp];
        sv[i][d]  = qkv[(((size_t)b * 192 + 128 + cq) * 16384) + sp];
    }
    __syncthreads();
    float logits[64];
    float mx = -1e30f;
#pragma unroll
    for (int j = 0; j < 64; j++) {
        float dot = 0.f;
#pragma unroll
        for (int d = 0; d < 8; d++) dot += q[d] * sk[j][d];
        float l = dot * ATTN_SCALE + rpb[relidx[i * 64 + j] * 8 + n];
        logits[j] = l;
        mx = fmaxf(mx, l);
    }
    float se = 0.f;
#pragma unroll
    for (int j = 0; j < 64; j++) { float e = expf(logits[j] - mx); logits[j] = e; se += e; }
    float inv = 1.f / se;
    float od[8];
#pragma unroll
    for (int d = 0; d < 8; d++) od[d] = 0.f;
#pragma unroll
    for (int j = 0; j < 64; j++) {
#pragma unroll
        for (int d = 0; d < 8; d++) od[d] += logits[j] * sv[j][d];
    }
#pragma unroll
    for (int d = 0; d < 8; d++)
        o[(((size_t)b * 64 + n * 8 + d) * 128 + hi) * 128 + wi] = od[d] * inv;
}

// ---------------- directional pools + add local ----------------
__global__ void poolsum_k(const float* __restrict__ o, const float* __restrict__ loc,
                          float* __restrict__ out)
{
    int idx = blockIdx.x * blockDim.x + threadIdx.x;
    int n = NB * NC * HW128 * HW128;
    if (idx >= n) return;
    int w = idx & 127, h = (idx >> 7) & 127;
    size_t chbase = (size_t)(idx >> 14) * 16384;
    float sx = 0.f;
#pragma unroll
    for (int t = -3; t <= 4; t++) {
        int r = h + t;
        if (r >= 0 && r <= 128) { if (r == 128) r = 126; sx += o[chbase + (size_t)r * 128 + w]; }
    }
    float sy = 0.f;
#pragma unroll
    for (int t = -3; t <= 4; t++) {
        int c = w + t;
        if (c >= 0 && c <= 128) { if (c == 128) c = 126; sy += o[chbase + (size_t)h * 128 + c]; }
    }
    out[idx] = (sx + sy) * 0.125f + loc[idx];
}

// ---------------- depthwise 8x8 conv (pad 3, zero boundary) + BN ----------------
__global__ void dwconv_k(const float* __restrict__ in, const float* __restrict__ w,
                         const float* __restrict__ bng, const float* __restrict__ bnb,
                         float* __restrict__ out)
{
    __shared__ float sIn[23 * 23];
    __shared__ float sWt[64];
    int tile = blockIdx.x;
    int tX = tile & 7, tY = tile >> 3;
    int c = blockIdx.y, b = blockIdx.z;
    int tid = threadIdx.y * 16 + threadIdx.x;
    if (tid < 64) sWt[tid] = w[c * 64 + tid];
    int h0 = tY * 16 - 3, w0 = tX * 16 - 3;
    const float* ip = in + (size_t)(b * 64 + c) * 16384;
    for (int t = tid; t < 23 * 23; t += 256) {
        int iy = t / 23, ix = t - iy * 23;
        int gy = h0 + iy, gx = w0 + ix;
        sIn[t] = (gy >= 0 && gy < 128 && gx >= 0 && gx < 128) ? ip[(size_t)gy * 128 + gx] : 0.f;
    }
    __syncthreads();
    float acc = 0.f;
#pragma unroll
    for (int i = 0; i < 8; i++)
#pragma unroll
        for (int j = 0; j < 8; j++)
            acc += sIn[(threadIdx.y + i) * 23 + threadIdx.x + j] * sWt[i * 8 + j];
    float v = acc * (bng[c] * BN_SC) + bnb[c];
    out[((size_t)(b * 64 + c) * 128 + tY * 16 + threadIdx.y) * 128 + tX * 16 + threadIdx.x] = v;
}

// ---------------- host ----------------
static dim3 convGridT(int Hout, int Wout, int Cout)
{
    return dim3(((Wout + 31) / 32) * ((Hout + 31) / 32), (Cout + 7) / 8, NB);
}

extern "C" void kernel_launch(void* const* d_in, const int* in_sizes, int n_in,
                              void* d_out, int out_size)
{
    const float* x       = (const float*)d_in[0];
    const float* w_qkv   = (const float*)d_in[1];
    const float* w_l1    = (const float*)d_in[2];
    const float* gl1     = (const float*)d_in[3];
    const float* bl1     = (const float*)d_in[4];
    const float* w_l2    = (const float*)d_in[5];
    const float* gl2     = (const float*)d_in[6];
    const float* bl2     = (const float*)d_in[7];
    const float* f_cos   = (const float*)d_in[8];
    const float* f_sin   = (const float*)d_in[9];
    const float* gb_b1   = (const float*)d_in[10];
    const float* gb_b2   = (const float*)d_in[11];
    const float* gb_w    = (const float*)d_in[12];
    const float* w_post  = (const float*)d_in[13];
    const float* g_postp = (const float*)d_in[14];
    const float* b_postp = (const float*)d_in[15];
    const float* w_gc    = (const float*)d_in[16];
    const float* b_gc    = (const float*)d_in[17];
    const float* w_gc1   = (const float*)d_in[18];
    const float* b_gc1   = (const float*)d_in[19];
    const float* w_gc2   = (const float*)d_in[20];
    const float* b_gc2   = (const float*)d_in[21];
    const float* rpb     = (const float*)d_in[22];
    const float* w_dw    = (const float*)d_in[23];
    const float* g_proj  = (const float*)d_in[24];
    const float* b_proj  = (const float*)d_in[25];
    const float* w_pw    = (const float*)d_in[26];
    const int*   relidx  = (const int*)  d_in[27];
    float* out = (float*)d_out;

    float *loc, *qkv, *obuf, *sum, *dw, *xc, *xc2, *cr1, *ci1, *cr2, *ci2;
    float *pb, *qb, *rb, *sb, *tb, *ub, *vb, *wl, *bl, *wgab, *bgab;
    cudaGetSymbolAddress((void**)&loc,  g_local);
    cudaGetSymbolAddress((void**)&qkv,  g_qkv);
    cudaGetSymbolAddress((void**)&obuf, g_o);
    cudaGetSymbolAddress((void**)&sum,  g_sum);
    cudaGetSymbolAddress((void**)&dw,   g_dw);
    cudaGetSymbolAddress((void**)&xc,   g_xc);
    cudaGetSymbolAddress((void**)&xc2,  g_xc2);
    cudaGetSymbolAddress((void**)&cr1,  g_cr1);
    cudaGetSymbolAddress((void**)&ci1,  g_ci1);
    cudaGetSymbolAddress((void**)&cr2,  g_cr2);
    cudaGetSymbolAddress((void**)&ci2,  g_ci2);
    cudaGetSymbolAddress((void**)&pb,   g_p);
    cudaGetSymbolAddress((void**)&qb,   g_q);
    cudaGetSymbolAddress((void**)&rb,   g_r);
    cudaGetSymbolAddress((void**)&sb,   g_s);
    cudaGetSymbolAddress((void**)&tb,   g_t);
    cudaGetSymbolAddress((void**)&ub,   g_u);
    cudaGetSymbolAddress((void**)&vb,   g_v);
    cudaGetSymbolAddress((void**)&wl,   g_wl);
    cudaGetSymbolAddress((void**)&bl,   g_bl);
    cudaGetSymbolAddress((void**)&wgab, g_wgab);
    cudaGetSymbolAddress((void**)&bgab, g_bgab);

    const int T = 256;

    // weight prep + DFT tables
    prep_l_k<<<(64*64*9 + T - 1)/T, T>>>(w_l1, gl1, bl1, w_l2, gl2, bl2);
    prep_gab_k<<<(64*64*9 + T - 1)/T, T>>>(f_cos, f_sin, gb_b1, gb_b2);
    initdft_k<<<(NS*NS + T - 1)/T, T>>>();

    // local pre (merged l1+l2, BN folded into weights)
    conv_t<3,1><<<convGridT(128,128,64), T>>>(x, wl, bl, nullptr, nullptr, loc,
                                              128,128, 64,64,0, 1, 128,128, 0,0);
    // merged gabor cos+sin conv (valid, 128->126)
    conv_t<3,1><<<convGridT(126,126,64), T>>>(loc, wgab, bgab, nullptr, nullptr, xc,
                                              128,128, 64,64,0, 0, 126,126, 0,0);
    // DFT high-pass: F X -> (Y F, mask) -> F* G -> (Re(U F*), mag+combine)
    dim3 gg(2, 2, NIMG), bbk(16, 16);
    cgemm_t<1><<<gg, bbk>>>(xc,  nullptr, cr1, ci1, nullptr, nullptr, nullptr);
    cgemm_t<2><<<gg, bbk>>>(cr1, ci1,     cr2, ci2, nullptr, nullptr, nullptr);
    cgemm_t<3><<<gg, bbk>>>(cr2, ci2,     cr1, ci1, nullptr, nullptr, nullptr);
    cgemm_t<4><<<gg, bbk>>>(cr1, ci1,     nullptr, nullptr, xc, gb_w, xc2);
    // post conv + bn + relu6
    conv_t<3,1><<<convGridT(126,126,64), T>>>(xc2, w_post, nullptr, g_postp, b_postp, pb,
                                              126,126, 64,64,0, 1, 126,126, 2,0);
    mp21_k<<<(NIMG*125*125 + T - 1)/T, T>>>(pb, qb);
    conv_t<3,2><<<convGridT(62,62,64), T>>>(qb, w_gc, b_gc, nullptr, nullptr, rb,
                                            125,125, 64,64,0, 0, 62,62, 1,0);
    mp22_k<<<(NIMG*31*31 + T - 1)/T, T>>>(rb, sb);
    resize_k<<<(NIMG*16384 + T - 1)/T, T>>>(sb, tb);
    conv_t<3,1><<<convGridT(128,128,64), T>>>(tb, w_gc1, b_gc1, nullptr, nullptr, ub,
                                              128,128, 64,64,0, 1, 128,128, 1,0);
    conv_t<1,1><<<convGridT(128,128,64), T>>>(ub, w_gc2, b_gc2, nullptr, nullptr, vb,
                                              128,128, 64,64,0, 0, 128,128, 0,0);
    lsm_k<<<(NB*16384 + T - 1)/T, T>>>(vb, loc);
    // global branch
    conv_t<1,1><<<convGridT(128,128,192), T>>>(x, w_qkv, nullptr, nullptr, nullptr, qkv,
                                               128,128, 192,192,0, 0, 128,128, 0,0);
    attn_k<<<dim3(256, NH_, NB), 64>>>(qkv, rpb, relidx, obuf);
    poolsum_k<<<(NB*NC*16384 + T - 1)/T, T>>>(obuf, loc, sum);
    dwconv_k<<<dim3(64, 64, NB), dim3(16,16)>>>(sum, w_dw, g_proj, b_proj, dw);
    conv_t<1,1><<<convGridT(128,128,64), T>>>(dw, w_pw, nullptr, nullptr, nullptr, out,
                                              128,128, 64,64,0, 0, 128,128, 0,0);
    (void)in_sizes; (void)n_in; (void)out_size;
}